// round 6
// baseline (speedup 1.0000x reference)
#include <cuda_runtime.h>
#include <cuda_fp16.h>
#include <cstdint>

// Batch Conv1D, implicit-im2col GEMM on mma.sync (HMMA fp16/fp32 accum).
// Round 6: R5 tap-reuse kernel + x fp32->fp16 conversion fused into A staging
// (xconv pre-pass eliminated; W pre-pass kept, ~2us).
//
// Floor model: legacy mma.sync fp16 on sm_103 = 512 MAC/cyc/SM (~286 TF/s chip).
// R5 GEMM runs at that floor; fusing A conversion adds ~8KB/step L1 traffic
// (51KB/step total, below the 72KB/step that also ran at floor in R3), so the
// GEMM should stay at ~360us while the 56us pre-pass disappears.
//
// K ordered as (8 channel-chunks x 3 taps); one x tile of 130 rows x 32 ch
// serves all 3 taps (ldmatrix row base shifts by tap).

namespace {

constexpr int LOUT = 1022;
constexpr int NTHREADS = 128;

constexpr int A_STRIDE = 80;              // 32 fp16 (64B) + 16B pad
constexpr int A_ROWS   = 130;             // 128 outputs + 2 taps
constexpr int A_BYTES  = A_ROWS * A_STRIDE;   // 10400
constexpr int B_STRIDE = 272;             // 128 fp16 (256B) + 16B pad
constexpr int B_BYTES  = 32 * B_STRIDE;   // 8704

__device__ __half g_wf16[768 * 256];

// ---------------- PTX helpers ----------------

__device__ __forceinline__ uint32_t smem_u32(const void* p) {
    return (uint32_t)__cvta_generic_to_shared(p);
}
__device__ __forceinline__ void cp16(uint32_t dst, const void* src) {
    asm volatile("cp.async.cg.shared.global [%0], [%1], 16;" :: "r"(dst), "l"(src));
}
__device__ __forceinline__ void cp_commit() {
    asm volatile("cp.async.commit_group;" ::: "memory");
}
__device__ __forceinline__ void cp_wait0() {
    asm volatile("cp.async.wait_group 0;" ::: "memory");
}
__device__ __forceinline__ void ldsm4(uint32_t (&r)[4], uint32_t addr) {
    asm volatile("ldmatrix.sync.aligned.m8n8.x4.shared.b16 {%0,%1,%2,%3}, [%4];"
                 : "=r"(r[0]), "=r"(r[1]), "=r"(r[2]), "=r"(r[3]) : "r"(addr));
}
__device__ __forceinline__ void ldsm4t(uint32_t (&r)[4], uint32_t addr) {
    asm volatile("ldmatrix.sync.aligned.m8n8.x4.trans.shared.b16 {%0,%1,%2,%3}, [%4];"
                 : "=r"(r[0]), "=r"(r[1]), "=r"(r[2]), "=r"(r[3]) : "r"(addr));
}
__device__ __forceinline__ void mma16816(float (&c)[4], const uint32_t (&a)[4],
                                         uint32_t b0, uint32_t b1) {
    asm volatile(
        "mma.sync.aligned.m16n8k16.row.col.f32.f16.f16.f32 "
        "{%0,%1,%2,%3}, {%4,%5,%6,%7}, {%8,%9}, {%0,%1,%2,%3};"
        : "+f"(c[0]), "+f"(c[1]), "+f"(c[2]), "+f"(c[3])
        : "r"(a[0]), "r"(a[1]), "r"(a[2]), "r"(a[3]), "r"(b0), "r"(b1));
}
__device__ __forceinline__ uint32_t pack_h2(float a, float b) {
    __half2 h = __floats2half2_rn(a, b);
    return *(uint32_t*)&h;
}

// ---------------- pre-pass: W fp32 -> fp16 (tiny) ----------------

__global__ void wconv_kernel(const float* __restrict__ W) {
    int i = blockIdx.x * 256 + threadIdx.x;
    g_wf16[i] = __float2half_rn(W[i]);
}

// ---------------- main GEMM ----------------

__global__ __launch_bounds__(NTHREADS, 2)
void conv1d_hmma_kernel(const float* __restrict__ x,
                        const float* __restrict__ bias,
                        float* __restrict__ out)
{
    __shared__ __align__(128) uint8_t smA[2][A_BYTES];
    __shared__ __align__(128) uint8_t smB[2][B_BYTES];

    const int tid  = threadIdx.x;
    const int wid  = tid >> 5;
    const int lane = tid & 31;

    const int f0  = blockIdx.x * 128;
    const int l0  = blockIdx.y * 128;
    const int img = blockIdx.z;

    const float* xb = x   + (size_t)img * (1024 * 256);
    float*       ob = out + (size_t)img * (LOUT * 256);

    // 2x2 warp grid, 64x64 warp tiles
    const int wm = (wid >> 1) * 64;
    const int wn = (wid & 1) * 64;

    const uint32_t sAb[2] = { smem_u32(&smA[0][0]), smem_u32(&smA[1][0]) };
    const uint32_t sBb[2] = { smem_u32(&smB[0][0]), smem_u32(&smB[1][0]) };

    // ldmatrix lane bases
    const uint32_t a_lane = (uint32_t)(wm + (lane & 15)) * A_STRIDE + (lane >> 4) * 16;
    const uint32_t b_lane = (uint32_t)(lane & 15) * B_STRIDE
                          + (uint32_t)(wn + (lane >> 4) * 8) * 2;

    // ---- A staging: rows 0..129, channels [c*32, c*32+32), fp32 LDG -> cvt -> STS
    auto stageRowA = [&](int row, int c, int buf) {
        const int xr = l0 + row;
        const float* s = xb + (size_t)(xr < 1024 ? xr : 1023) * 256 + c * 32;
        float4 v[8];
        #pragma unroll
        for (int q = 0; q < 8; ++q) v[q] = *(const float4*)(s + q * 4);
        uint8_t* d = (buf ? &smA[1][0] : &smA[0][0]) + (uint32_t)row * A_STRIDE;
        #pragma unroll
        for (int h = 0; h < 2; ++h) {
            uint4 u;
            u.x = pack_h2(v[h * 4 + 0].x, v[h * 4 + 0].y);
            u.y = pack_h2(v[h * 4 + 0].z, v[h * 4 + 0].w);
            u.z = pack_h2(v[h * 4 + 1].x, v[h * 4 + 1].y);
            u.w = pack_h2(v[h * 4 + 1].z, v[h * 4 + 1].w);
            uint4 u2;
            u2.x = pack_h2(v[h * 4 + 2].x, v[h * 4 + 2].y);
            u2.y = pack_h2(v[h * 4 + 2].z, v[h * 4 + 2].w);
            u2.z = pack_h2(v[h * 4 + 3].x, v[h * 4 + 3].y);
            u2.w = pack_h2(v[h * 4 + 3].z, v[h * 4 + 3].w);
            *(uint4*)(d + h * 32)      = u;
            *(uint4*)(d + h * 32 + 16) = u2;
        }
    };
    auto stageA = [&](int c, int buf) {
        stageRowA(tid, c, buf);
        if (tid < 2) stageRowA(128 + tid, c, buf);
    };

    // ---- B staging via cp.async (fp16, pre-converted W) ----
    auto stageB = [&](int tap, int c, int buf) {
        const int kr = tap * 256 + c * 32 + (tid >> 2);
        const __half* s = g_wf16 + (size_t)kr * 256 + f0 + (tid & 3) * 32;
        const uint32_t d = sBb[buf] + (uint32_t)(tid >> 2) * B_STRIDE + (tid & 3) * 64;
        cp16(d,      s);
        cp16(d + 16, s + 8);
        cp16(d + 32, s + 16);
        cp16(d + 48, s + 24);
    };

    float acc[4][8][4];
    #pragma unroll
    for (int mt = 0; mt < 4; ++mt)
        #pragma unroll
        for (int nt = 0; nt < 8; ++nt)
            #pragma unroll
            for (int q = 0; q < 4; ++q)
                acc[mt][nt][q] = 0.f;

    // prologue: stage A(c=0), B(step 0)
    stageB(0, 0, 0);
    cp_commit();
    stageA(0, 0);
    cp_wait0();
    __syncthreads();

    for (int c = 0; c < 8; ++c) {
        #pragma unroll
        for (int tap = 0; tap < 3; ++tap) {
            const int s = c * 3 + tap;
            const bool more = (s + 1) < 24;

            // prefetch next B (async, flies under the MMA block)
            if (more) {
                const int ntap = (tap == 2) ? 0 : tap + 1;
                const int nc   = (tap == 2) ? c + 1 : c;
                stageB(ntap, nc, (s + 1) & 1);
                cp_commit();
            }
            // prefetch next A chunk (fp32 -> fp16, sync; hidden by peer CTA's MMAs)
            if (tap == 0 && c + 1 < 8) stageA(c + 1, (c + 1) & 1);

            // MMA block: A row base shifted by tap (conv tap-reuse)
            const uint32_t sA = sAb[c & 1] + (uint32_t)tap * A_STRIDE;
            const uint32_t sB = sBb[s & 1];
            #pragma unroll
            for (int ks = 0; ks < 2; ++ks) {
                uint32_t af[4][4];
                #pragma unroll
                for (int mt = 0; mt < 4; ++mt)
                    ldsm4(af[mt], sA + a_lane + mt * (16 * A_STRIDE) + ks * 32);
                uint32_t bf[4][4];
                #pragma unroll
                for (int n2 = 0; n2 < 4; ++n2)
                    ldsm4t(bf[n2], sB + b_lane + ks * (16 * B_STRIDE) + n2 * 32);
                #pragma unroll
                for (int mt = 0; mt < 4; ++mt)
                    #pragma unroll
                    for (int n2 = 0; n2 < 4; ++n2) {
                        mma16816(acc[mt][2 * n2],     af[mt], bf[n2][0], bf[n2][1]);
                        mma16816(acc[mt][2 * n2 + 1], af[mt], bf[n2][2], bf[n2][3]);
                    }
            }

            if (more) cp_wait0();
            __syncthreads();
        }
    }

    // ---- epilogue: bias + guarded store from registers ----
    const int g  = lane >> 2;
    const int tq = lane & 3;
    #pragma unroll
    for (int nt = 0; nt < 8; ++nt) {
        const int col = f0 + wn + nt * 8 + tq * 2;
        const float b0 = __ldg(bias + col);
        const float b1 = __ldg(bias + col + 1);
        #pragma unroll
        for (int mt = 0; mt < 4; ++mt) {
            const int r = l0 + wm + mt * 16 + g;
            if (r < LOUT) {
                float2 v = make_float2(acc[mt][nt][0] + b0, acc[mt][nt][1] + b1);
                *(float2*)(ob + (size_t)r * 256 + col) = v;
            }
            if (r + 8 < LOUT) {
                float2 v = make_float2(acc[mt][nt][2] + b0, acc[mt][nt][3] + b1);
                *(float2*)(ob + (size_t)(r + 8) * 256 + col) = v;
            }
        }
    }
}

}  // namespace

extern "C" void kernel_launch(void* const* d_in, const int* in_sizes, int n_in,
                              void* d_out, int out_size)
{
    const float* x  = (const float*)d_in[0];   // [8,32,1024,256]
    const float* w  = (const float*)d_in[1];   // [3,256,256]
    const float* b  = (const float*)d_in[2];   // [256]
    float* out      = (float*)d_out;           // [8,32,1022,256]

    wconv_kernel<<<768, 256>>>(w);             // tiny: W fp32 -> fp16

    dim3 grid(2, 8, 256);                      // f-tiles, m-tiles, images
    conv1d_hmma_kernel<<<grid, NTHREADS>>>(x, b, out);
}

// round 7
// speedup vs baseline: 1.0733x; 1.0733x over previous
#include <cuda_runtime.h>
#include <cuda_fp16.h>
#include <cstdint>

// Batch Conv1D, implicit-im2col GEMM on mma.sync (HMMA fp16/fp32 accum).
// Round 7: R5 tap-reuse skeleton (runs at the 1024 MAC/cyc/SM HMMA floor) with
// x conversion fused correctly: cp.async stages fp32 x into smem (latency
// hidden like B), a conflict-free smem->smem cvt pass (during the tap-1 step)
// produces the fp16 A tile. Eliminates the 56us xconv pre-pass without the
// R6 mistake (synchronous LDG exposing DRAM latency inside the barriered loop).
//
// K ordered as (8 channel-chunks x 3 taps); one x tile of 130 rows x 32 ch
// serves all 3 taps (ldmatrix row base shifts by tap).

namespace {

constexpr int LOUT = 1022;
constexpr int NTHREADS = 128;

constexpr int A_STRIDE  = 80;                 // 32 fp16 (64B) + 16B pad
constexpr int A_ROWS    = 130;                // 128 outputs + 2 taps
constexpr int A_BYTES   = 10496;              // 130*80=10400, padded to 128B mult
constexpr int B_STRIDE  = 272;                // 128 fp16 (256B) + 16B pad
constexpr int B_BYTES   = 8704;               // 32*272
constexpr int F_STRIDE  = 144;                // 32 fp32 (128B) + 16B pad

// dynamic smem layout
constexpr int OFF_A0  = 0;
constexpr int OFF_A1  = OFF_A0 + A_BYTES;     // 10496
constexpr int OFF_B0  = OFF_A1 + A_BYTES;     // 20992
constexpr int OFF_B1  = OFF_B0 + B_BYTES;     // 29696
constexpr int OFF_F32 = OFF_B1 + B_BYTES;     // 38400
constexpr int SMEM_TOTAL = OFF_F32 + A_ROWS * F_STRIDE + 96;   // 57216

__device__ __half g_wf16[768 * 256];

// ---------------- PTX helpers ----------------

__device__ __forceinline__ uint32_t smem_u32(const void* p) {
    return (uint32_t)__cvta_generic_to_shared(p);
}
__device__ __forceinline__ void cp16(uint32_t dst, const void* src) {
    asm volatile("cp.async.cg.shared.global [%0], [%1], 16;" :: "r"(dst), "l"(src));
}
__device__ __forceinline__ void cp_commit() {
    asm volatile("cp.async.commit_group;" ::: "memory");
}
__device__ __forceinline__ void cp_wait0() {
    asm volatile("cp.async.wait_group 0;" ::: "memory");
}
__device__ __forceinline__ void ldsm4(uint32_t (&r)[4], uint32_t addr) {
    asm volatile("ldmatrix.sync.aligned.m8n8.x4.shared.b16 {%0,%1,%2,%3}, [%4];"
                 : "=r"(r[0]), "=r"(r[1]), "=r"(r[2]), "=r"(r[3]) : "r"(addr));
}
__device__ __forceinline__ void ldsm4t(uint32_t (&r)[4], uint32_t addr) {
    asm volatile("ldmatrix.sync.aligned.m8n8.x4.trans.shared.b16 {%0,%1,%2,%3}, [%4];"
                 : "=r"(r[0]), "=r"(r[1]), "=r"(r[2]), "=r"(r[3]) : "r"(addr));
}
__device__ __forceinline__ void mma16816(float (&c)[4], const uint32_t (&a)[4],
                                         uint32_t b0, uint32_t b1) {
    asm volatile(
        "mma.sync.aligned.m16n8k16.row.col.f32.f16.f16.f32 "
        "{%0,%1,%2,%3}, {%4,%5,%6,%7}, {%8,%9}, {%0,%1,%2,%3};"
        : "+f"(c[0]), "+f"(c[1]), "+f"(c[2]), "+f"(c[3])
        : "r"(a[0]), "r"(a[1]), "r"(a[2]), "r"(a[3]), "r"(b0), "r"(b1));
}
__device__ __forceinline__ uint32_t pack_h2(float a, float b) {
    __half2 h = __floats2half2_rn(a, b);
    return *(uint32_t*)&h;
}

// ---------------- pre-pass: W fp32 -> fp16 (tiny) ----------------

__global__ void wconv_kernel(const float* __restrict__ W) {
    int i = blockIdx.x * 256 + threadIdx.x;
    g_wf16[i] = __float2half_rn(W[i]);
}

// ---------------- main GEMM ----------------

__global__ __launch_bounds__(NTHREADS, 2)
void conv1d_hmma_kernel(const float* __restrict__ x,
                        const float* __restrict__ bias,
                        float* __restrict__ out)
{
    extern __shared__ __align__(128) uint8_t smem[];
    const uint32_t sm = smem_u32(smem);

    const int tid  = threadIdx.x;
    const int wid  = tid >> 5;
    const int lane = tid & 31;

    const int f0  = blockIdx.x * 128;
    const int l0  = blockIdx.y * 128;
    const int img = blockIdx.z;

    const float* xb = x   + (size_t)img * (1024 * 256);
    float*       ob = out + (size_t)img * (LOUT * 256);

    // 2x2 warp grid, 64x64 warp tiles
    const int wm = (wid >> 1) * 64;
    const int wn = (wid & 1) * 64;

    const uint32_t sAb[2] = { sm + OFF_A0, sm + OFF_A1 };
    const uint32_t sBb[2] = { sm + OFF_B0, sm + OFF_B1 };
    const uint32_t sF32   = sm + OFF_F32;

    // ldmatrix lane bases
    const uint32_t a_lane = (uint32_t)(wm + (lane & 15)) * A_STRIDE + (lane >> 4) * 16;
    const uint32_t b_lane = (uint32_t)(lane & 15) * B_STRIDE
                          + (uint32_t)(wn + (lane >> 4) * 8) * 2;

    // ---- A fp32 staging via cp.async: rows 0..129 x 32 fp32 ----
    auto stageAF32 = [&](int c) {
        {
            const int xr = l0 + tid;
            const float* s = xb + (size_t)(xr < 1024 ? xr : 1023) * 256 + c * 32;
            const uint32_t d = sF32 + (uint32_t)tid * F_STRIDE;
            #pragma unroll
            for (int q = 0; q < 8; ++q) cp16(d + q * 16, s + q * 4);
        }
        if (tid < 2) {
            const int r  = 128 + tid;
            const int xr = l0 + r;
            const float* s = xb + (size_t)(xr < 1024 ? xr : 1023) * 256 + c * 32;
            const uint32_t d = sF32 + (uint32_t)r * F_STRIDE;
            #pragma unroll
            for (int q = 0; q < 8; ++q) cp16(d + q * 16, s + q * 4);
        }
    };

    // ---- convert fp32 staging -> fp16 A tile (conflict-free LDS/STS) ----
    auto convRow = [&](int row, int buf) {
        const float* s = (const float*)(smem + OFF_F32 + (uint32_t)row * F_STRIDE);
        float4 v[4];
        uint8_t* d = smem + (buf ? OFF_A1 : OFF_A0) + (uint32_t)row * A_STRIDE;
        #pragma unroll
        for (int h = 0; h < 2; ++h) {
            v[0] = *(const float4*)(s + h * 16 + 0);
            v[1] = *(const float4*)(s + h * 16 + 4);
            v[2] = *(const float4*)(s + h * 16 + 8);
            v[3] = *(const float4*)(s + h * 16 + 12);
            uint4 u;
            u.x = pack_h2(v[0].x, v[0].y); u.y = pack_h2(v[0].z, v[0].w);
            u.z = pack_h2(v[1].x, v[1].y); u.w = pack_h2(v[1].z, v[1].w);
            uint4 u2;
            u2.x = pack_h2(v[2].x, v[2].y); u2.y = pack_h2(v[2].z, v[2].w);
            u2.z = pack_h2(v[3].x, v[3].y); u2.w = pack_h2(v[3].z, v[3].w);
            *(uint4*)(d + h * 32)      = u;
            *(uint4*)(d + h * 32 + 16) = u2;
        }
    };
    auto convA = [&](int buf) {
        convRow(tid, buf);
        if (tid < 2) convRow(128 + tid, buf);
    };

    // ---- B staging via cp.async (fp16, pre-converted W) ----
    auto stageB = [&](int tap, int c, int buf) {
        const int kr = tap * 256 + c * 32 + (tid >> 2);
        const __half* s = g_wf16 + (size_t)kr * 256 + f0 + (tid & 3) * 32;
        const uint32_t d = sBb[buf] + (uint32_t)(tid >> 2) * B_STRIDE + (tid & 3) * 64;
        cp16(d,      s);
        cp16(d + 16, s + 8);
        cp16(d + 32, s + 16);
        cp16(d + 48, s + 24);
    };

    float acc[4][8][4];
    #pragma unroll
    for (int mt = 0; mt < 4; ++mt)
        #pragma unroll
        for (int nt = 0; nt < 8; ++nt)
            #pragma unroll
            for (int q = 0; q < 4; ++q)
                acc[mt][nt][q] = 0.f;

    // ---- prologue: stage fp32 A(0) + B(0), convert A(0) ----
    stageAF32(0);
    stageB(0, 0, 0);
    cp_commit();
    cp_wait0();
    __syncthreads();
    convA(0);
    __syncthreads();

    for (int c = 0; c < 8; ++c) {
        #pragma unroll
        for (int tap = 0; tap < 3; ++tap) {
            const int s = c * 3 + tap;
            const bool more = (s + 1) < 24;

            // prefetch next B; at tap 0 also stage next chunk's fp32 A (both async)
            if (more) {
                const int ntap = (tap == 2) ? 0 : tap + 1;
                const int nc   = (tap == 2) ? c + 1 : c;
                stageB(ntap, nc, (s + 1) & 1);
            }
            if (tap == 0 && c + 1 < 8) stageAF32(c + 1);
            if (more) cp_commit();

            // MMA block: A row base shifted by tap (conv tap-reuse)
            const uint32_t sA = sAb[c & 1] + (uint32_t)tap * A_STRIDE;
            const uint32_t sB = sBb[s & 1];
            #pragma unroll
            for (int ks = 0; ks < 2; ++ks) {
                uint32_t af[4][4];
                #pragma unroll
                for (int mt = 0; mt < 4; ++mt)
                    ldsm4(af[mt], sA + a_lane + mt * (16 * A_STRIDE) + ks * 32);
                uint32_t bf[4][4];
                #pragma unroll
                for (int n2 = 0; n2 < 4; ++n2)
                    ldsm4t(bf[n2], sB + b_lane + ks * (16 * B_STRIDE) + n2 * 32);
                #pragma unroll
                for (int mt = 0; mt < 4; ++mt)
                    #pragma unroll
                    for (int n2 = 0; n2 < 4; ++n2) {
                        mma16816(acc[mt][2 * n2],     af[mt], bf[n2][0], bf[n2][1]);
                        mma16816(acc[mt][2 * n2 + 1], af[mt], bf[n2][2], bf[n2][3]);
                    }
            }

            // convert next chunk's A during the tap-1 step (fp32 arrived at end
            // of tap 0: wait0 + barrier already ordered it; fp16 dest buffer is
            // idle until chunk c+1)
            if (tap == 1 && c + 1 < 8) convA((c + 1) & 1);

            if (more) cp_wait0();
            __syncthreads();
        }
    }

    // ---- epilogue: bias + guarded store from registers ----
    const int g  = lane >> 2;
    const int tq = lane & 3;
    #pragma unroll
    for (int nt = 0; nt < 8; ++nt) {
        const int col = f0 + wn + nt * 8 + tq * 2;
        const float b0 = __ldg(bias + col);
        const float b1 = __ldg(bias + col + 1);
        #pragma unroll
        for (int mt = 0; mt < 4; ++mt) {
            const int r = l0 + wm + mt * 16 + g;
            if (r < LOUT) {
                float2 v = make_float2(acc[mt][nt][0] + b0, acc[mt][nt][1] + b1);
                *(float2*)(ob + (size_t)r * 256 + col) = v;
            }
            if (r + 8 < LOUT) {
                float2 v = make_float2(acc[mt][nt][2] + b0, acc[mt][nt][3] + b1);
                *(float2*)(ob + (size_t)(r + 8) * 256 + col) = v;
            }
        }
    }
}

}  // namespace

extern "C" void kernel_launch(void* const* d_in, const int* in_sizes, int n_in,
                              void* d_out, int out_size)
{
    const float* x  = (const float*)d_in[0];   // [8,32,1024,256]
    const float* w  = (const float*)d_in[1];   // [3,256,256]
    const float* b  = (const float*)d_in[2];   // [256]
    float* out      = (float*)d_out;           // [8,32,1022,256]

    wconv_kernel<<<768, 256>>>(w);             // tiny: W fp32 -> fp16

    cudaFuncSetAttribute(conv1d_hmma_kernel,
                         cudaFuncAttributeMaxDynamicSharedMemorySize, SMEM_TOTAL);

    dim3 grid(2, 8, 256);                      // f-tiles, m-tiles, images
    conv1d_hmma_kernel<<<grid, NTHREADS, SMEM_TOTAL>>>(x, b, out);
}